// round 1
// baseline (speedup 1.0000x reference)
#include <cuda_runtime.h>

#define NB 4
#define NN 4096
#define ND 32
#define NC 256

// Scratch (device globals: allocation-free rule)
__device__ float g_fbuf[NB*NN*ND];   // 2 MB
__device__ float g_gbuf[NB*NN*ND];   // 2 MB
__device__ float g_hbuf[NB*NN*NC];   // 16 MB

// ---- packed f32x2 helpers (sm_103a) ----
__device__ __forceinline__ unsigned long long pk2(float a, float b) {
    unsigned long long r;
    asm("mov.b64 %0, {%1, %2};" : "=l"(r) : "f"(a), "f"(b));
    return r;
}
__device__ __forceinline__ void fma2(unsigned long long& d, unsigned long long a, unsigned long long b) {
    asm("fma.rn.f32x2 %0, %1, %2, %0;" : "+l"(d) : "l"(a), "l"(b));
}
__device__ __forceinline__ unsigned long long mul2(unsigned long long a, unsigned long long b) {
    unsigned long long r;
    asm("mul.rn.f32x2 %0, %1, %2;" : "=l"(r) : "l"(a), "l"(b));
    return r;
}
__device__ __forceinline__ void unpk2(unsigned long long v, float& a, float& b) {
    asm("mov.b64 {%0, %1}, %2;" : "=f"(a), "=f"(b) : "l"(v));
}

// ============================================================================
// Projection kernel: f = xW_f+b_f, g = xW_g+b_g, h = xW_h+b_h
// 256 CTAs x 256 threads, 64 rows per CTA. Dynamic smem:
//   xs[64][257] (x tile, padded) + ws[256][64] (weight panel)
// ============================================================================
#define PROJ_SMEM_BYTES ((64*257 + 256*64)*4)

__global__ __launch_bounds__(256) void proj_kernel(
    const float* __restrict__ x,
    const float* __restrict__ Wf, const float* __restrict__ bf,
    const float* __restrict__ Wg, const float* __restrict__ bg,
    const float* __restrict__ Wh, const float* __restrict__ bh)
{
    extern __shared__ float sm[];
    float* xs = sm;               // [64][257]
    float* ws = sm + 64*257;      // [256][64]
    const int t  = threadIdx.x;
    const int R0 = blockIdx.x * 64;   // global flattened row (b*N+n)

    // load x tile [64][256] (coalesced float4)
    {
        const float4* xg = (const float4*)(x + R0*NC);
        #pragma unroll
        for (int s = 0; s < 16; s++) {
            int idx = t + 256*s;      // 0..4095 float4s
            int row = idx >> 6;
            int k4  = idx & 63;
            float4 v = xg[idx];
            float* dst = &xs[row*257 + k4*4];
            dst[0]=v.x; dst[1]=v.y; dst[2]=v.z; dst[3]=v.w;
        }
    }

    const int c0 = (t & 15) * 4;   // 4 output cols per thread
    const int r0 = (t >> 4) * 4;   // 4 rows per thread

    // phase 0: f|g (64 cols). phases 1..4: Wh panels of 64 cols
    for (int ph = 0; ph < 5; ph++) {
        __syncthreads();
        if (ph == 0) {
            #pragma unroll
            for (int s = 0; s < 32; s++) {
                int idx = t + 256*s;          // 0..8191
                int k = idx >> 5, c = idx & 31;
                ws[k*64 + c]      = Wf[idx];
                ws[k*64 + 32 + c] = Wg[idx];
            }
        } else {
            const float* whp = Wh + (ph-1)*64;
            #pragma unroll
            for (int s = 0; s < 64; s++) {
                int idx = t + 256*s;          // 0..16383
                int k = idx >> 6, c = idx & 63;
                ws[k*64 + c] = whp[k*NC + c];
            }
        }
        __syncthreads();

        float acc[4][4];
        #pragma unroll
        for (int a=0;a<4;a++)
            #pragma unroll
            for (int bq=0;bq<4;bq++) acc[a][bq]=0.f;

        #pragma unroll 4
        for (int k = 0; k < 256; k++) {
            float4 wv = *(const float4*)&ws[k*64 + c0];
            float xv[4];
            #pragma unroll
            for (int rr=0; rr<4; rr++) xv[rr] = xs[(r0+rr)*257 + k];
            #pragma unroll
            for (int rr=0; rr<4; rr++) {
                acc[rr][0] = fmaf(xv[rr], wv.x, acc[rr][0]);
                acc[rr][1] = fmaf(xv[rr], wv.y, acc[rr][1]);
                acc[rr][2] = fmaf(xv[rr], wv.z, acc[rr][2]);
                acc[rr][3] = fmaf(xv[rr], wv.w, acc[rr][3]);
            }
        }

        if (ph == 0) {
            #pragma unroll
            for (int rr=0; rr<4; rr++) {
                int grow = R0 + r0 + rr;
                #pragma unroll
                for (int q=0; q<4; q++) {
                    int c = c0 + q;
                    if (c < 32) g_fbuf[grow*ND + c]        = acc[rr][q] + bf[c];
                    else        g_gbuf[grow*ND + (c-32)]   = acc[rr][q] + bg[c-32];
                }
            }
        } else {
            #pragma unroll
            for (int rr=0; rr<4; rr++) {
                int grow = R0 + r0 + rr;
                #pragma unroll
                for (int q=0; q<4; q++) {
                    int c = (ph-1)*64 + c0 + q;
                    g_hbuf[grow*NC + c] = acc[rr][q] + bh[c];
                }
            }
        }
    }
}

// ============================================================================
// Flash-attention kernel. Grid (N/32, B), 256 threads, BM=BN=32.
// Each CTA: 32 query rows. Online softmax, f32x2-packed PV accumulation.
// Thread map (PV): rowgroup rg=t>>5 owns 4 rows, lane cg=t&31 owns channels
// {cg+32i}, i=0..7 (conflict-free LDS).
// ============================================================================
__global__ __launch_bounds__(256, 2) void attn_kernel(
    const float* __restrict__ x, float* __restrict__ out)
{
    __shared__ float g_s[32][33];
    __shared__ float f_s[32*32];
    __shared__ float h_s[32*256];
    __shared__ float p_s[32*32];        // [j][r]
    __shared__ float pmax_s[8][32];
    __shared__ float psum_s[8][32];
    __shared__ float mrow[32];
    __shared__ float scale_s[32];

    const int t  = threadIdx.x;
    const int r  = t & 31;     // s-row / channel lane
    const int jg = t >> 5;     // j-group / row-group
    const int r0 = jg * 4;
    const int b  = blockIdx.y;
    const int q0 = blockIdx.x * 32;
    const int base_q = b*NN + q0;

    // stage g tile into padded smem, then per-thread g row into registers
    {
        float4 v = ((const float4*)(g_gbuf + base_q*ND))[t];
        int row = t >> 3, k0 = (t & 7)*4;
        g_s[row][k0+0]=v.x; g_s[row][k0+1]=v.y; g_s[row][k0+2]=v.z; g_s[row][k0+3]=v.w;
    }
    __syncthreads();
    float greg[32];
    #pragma unroll
    for (int k=0;k<32;k++) greg[k] = g_s[r][k];

    float m_old = __int_as_float(0xff800000);   // -inf (warp0 lanes only)
    float lsum  = 0.f;
    unsigned long long a01[8], a23[8];          // rows (r0,r0+1) and (r0+2,r0+3)
    #pragma unroll
    for (int i=0;i<8;i++) { a01[i]=0ull; a23[i]=0ull; }

    for (int kb = 0; kb < NN/32; kb++) {
        const int base_k = b*NN + kb*32;
        ((float4*)f_s)[t] = ((const float4*)(g_fbuf + base_k*ND))[t];
        {
            const float4* hp = (const float4*)(g_hbuf + base_k*NC);
            float4* hd = (float4*)h_s;
            #pragma unroll
            for (int s2=0;s2<8;s2++) hd[t + 256*s2] = hp[t + 256*s2];
        }
        __syncthreads();

        // s = g . f^T : thread computes 4 j's for its row r
        float sv[4];
        #pragma unroll
        for (int jj=0;jj<4;jj++) {
            const float4* frow = (const float4*)&f_s[(r0+jj)*32];
            float acc = 0.f;
            #pragma unroll
            for (int k4=0;k4<8;k4++) {
                float4 fv = frow[k4];
                acc = fmaf(greg[k4*4+0], fv.x, acc);
                acc = fmaf(greg[k4*4+1], fv.y, acc);
                acc = fmaf(greg[k4*4+2], fv.z, acc);
                acc = fmaf(greg[k4*4+3], fv.w, acc);
            }
            sv[jj] = acc;
        }
        pmax_s[jg][r] = fmaxf(fmaxf(sv[0],sv[1]), fmaxf(sv[2],sv[3]));
        __syncthreads();

        if (t < 32) {
            float mt = pmax_s[0][t];
            #pragma unroll
            for (int q=1;q<8;q++) mt = fmaxf(mt, pmax_s[q][t]);
            float m_new = fmaxf(m_old, mt);
            scale_s[t] = __expf(m_old - m_new);
            mrow[t] = m_new;
            m_old = m_new;
        }
        __syncthreads();

        // p = exp(s - m_new), transposed store p_s[j][r]
        {
            float mn = mrow[r];
            float ps = 0.f;
            #pragma unroll
            for (int jj=0;jj<4;jj++) {
                float p = __expf(sv[jj] - mn);
                p_s[(r0+jj)*32 + r] = p;
                ps += p;
            }
            psum_s[jg][r] = ps;
        }
        __syncthreads();

        if (t < 32) {   // running denominator (overlaps PV of other warps)
            float s = psum_s[0][t];
            #pragma unroll
            for (int q=1;q<8;q++) s += psum_s[q][t];
            lsum = lsum * scale_s[t] + s;
        }

        // PV: rescale accumulators, then acc += p * h
        {
            float4 scv = *(const float4*)&scale_s[r0];
            unsigned long long s01 = pk2(scv.x, scv.y);
            unsigned long long s23 = pk2(scv.z, scv.w);
            #pragma unroll
            for (int i=0;i<8;i++) { a01[i]=mul2(a01[i],s01); a23[i]=mul2(a23[i],s23); }
            #pragma unroll 4
            for (int j=0;j<32;j++) {
                float4 pv = *(const float4*)&p_s[j*32 + r0];   // broadcast
                unsigned long long p01 = pk2(pv.x, pv.y);
                unsigned long long p23 = pk2(pv.z, pv.w);
                const float* hrow = &h_s[j*256 + r];
                #pragma unroll
                for (int i=0;i<8;i++) {
                    float hv = hrow[32*i];                      // conflict-free
                    unsigned long long hb = pk2(hv, hv);
                    fma2(a01[i], p01, hb);
                    fma2(a23[i], p23, hb);
                }
            }
        }
        __syncthreads();
    }

    if (t < 32) mrow[t] = lsum;
    __syncthreads();

    // epilogue: out = x + acc / l  (coalesced: lanes = consecutive channels)
    {
        float inv[4];
        #pragma unroll
        for (int rr=0;rr<4;rr++) inv[rr] = 1.0f / mrow[r0+rr];
        #pragma unroll
        for (int i=0;i<8;i++) {
            int c = r + 32*i;
            float v0,v1,v2,v3;
            unpk2(a01[i], v0, v1);
            unpk2(a23[i], v2, v3);
            int idx0 = (base_q + r0)*NC + c;
            out[idx0       ] = x[idx0       ] + v0*inv[0];
            out[idx0 +   NC] = x[idx0 +   NC] + v1*inv[1];
            out[idx0 + 2*NC] = x[idx0 + 2*NC] + v2*inv[2];
            out[idx0 + 3*NC] = x[idx0 + 3*NC] + v3*inv[3];
        }
    }
}

extern "C" void kernel_launch(void* const* d_in, const int* in_sizes, int n_in,
                              void* d_out, int out_size) {
    (void)in_sizes; (void)n_in; (void)out_size;
    const float* x  = (const float*)d_in[0];
    const float* Wf = (const float*)d_in[1];
    const float* bf = (const float*)d_in[2];
    const float* Wg = (const float*)d_in[3];
    const float* bg = (const float*)d_in[4];
    const float* Wh = (const float*)d_in[5];
    const float* bh = (const float*)d_in[6];
    float* out = (float*)d_out;

    cudaFuncSetAttribute(proj_kernel, cudaFuncAttributeMaxDynamicSharedMemorySize,
                         PROJ_SMEM_BYTES);

    proj_kernel<<<(NB*NN)/64, 256, PROJ_SMEM_BYTES>>>(x, Wf, bf, Wg, bg, Wh, bh);

    dim3 grid(NN/32, NB);
    attn_kernel<<<grid, 256>>>(x, out);
}

// round 3
// speedup vs baseline: 2.9905x; 2.9905x over previous
#include <cuda_runtime.h>
#include <cstdint>

#define NB 4
#define NN 4096
#define ND 32
#define NC 256
#define BM 64
#define BN 64

// ---------------- scratch (device globals; allocation-free rule) -----------
__device__ float d_ghi[NB*NN*ND];    // g rounded rna-tf32
__device__ float d_glo[NB*NN*ND];    // rna(g - g_hi)
__device__ float d_fThi[NB*ND*NN];   // f^T [b][d][key], rna-tf32
__device__ float d_fTlo[NB*ND*NN];
__device__ float d_h  [NB*NN*NC];    // h [b][key][c], rna-tf32

// ---------------- helpers ---------------------------------------------------
__device__ __forceinline__ uint32_t smem_u32(const void* p) {
    return (uint32_t)__cvta_generic_to_shared(p);
}
__device__ __forceinline__ void cpa16(uint32_t dst, const void* src) {
    asm volatile("cp.async.cg.shared.global [%0], [%1], 16;" :: "r"(dst), "l"(src));
}
__device__ __forceinline__ void cpa_commit() {
    asm volatile("cp.async.commit_group;" ::: "memory");
}
template<int N> __device__ __forceinline__ void cpa_wait() {
    asm volatile("cp.async.wait_group %0;" :: "n"(N) : "memory");
}
__device__ __forceinline__ float tf32r(float v) {
    uint32_t r;
    asm("cvt.rna.tf32.f32 %0, %1;" : "=r"(r) : "f"(v));
    return __uint_as_float(r);
}
// D = A(16x8 tf32) * B(8x8 tf32) + D, f32 accumulate
__device__ __forceinline__ void mma8(float* c, const uint32_t* a, const uint32_t* b) {
    asm volatile("mma.sync.aligned.m16n8k8.row.col.f32.tf32.tf32.f32 "
        "{%0,%1,%2,%3}, {%4,%5,%6,%7}, {%8,%9}, {%0,%1,%2,%3};"
        : "+f"(c[0]), "+f"(c[1]), "+f"(c[2]), "+f"(c[3])
        : "r"(a[0]), "r"(a[1]), "r"(a[2]), "r"(a[3]), "r"(b[0]), "r"(b[1]));
}
__device__ __forceinline__ uint32_t ldu(const float* p) {
    return __float_as_uint(*p);
}

// ============================================================================
// Projection kernel: f,g (hi/lo tf32 split; f transposed), h (tf32-rounded).
// ============================================================================
#define PROJ_SMEM_BYTES ((64*257 + 256*64)*4)

__global__ __launch_bounds__(256) void proj_kernel(
    const float* __restrict__ x,
    const float* __restrict__ Wf, const float* __restrict__ bf,
    const float* __restrict__ Wg, const float* __restrict__ bg,
    const float* __restrict__ Wh, const float* __restrict__ bh)
{
    extern __shared__ float sm[];
    float* xs = sm;               // [64][257]
    float* ws = sm + 64*257;      // [256][64]; reused as f staging
    const int t    = threadIdx.x;
    const int R0   = blockIdx.x * 64;
    const int bb   = R0 >> 12;
    const int key0 = R0 & (NN-1);

    {
        const float4* xg = (const float4*)(x + (size_t)R0*NC);
        #pragma unroll
        for (int s = 0; s < 16; s++) {
            int idx = t + 256*s;
            int row = idx >> 6, k4 = idx & 63;
            float4 v = xg[idx];
            float* dst = &xs[row*257 + k4*4];
            dst[0]=v.x; dst[1]=v.y; dst[2]=v.z; dst[3]=v.w;
        }
    }

    const int c0 = (t & 15) * 4;
    const int r0 = (t >> 4) * 4;

    for (int ph = 0; ph < 5; ph++) {
        __syncthreads();
        if (ph == 0) {
            #pragma unroll
            for (int s = 0; s < 32; s++) {
                int idx = t + 256*s;
                int k = idx >> 5, c = idx & 31;
                ws[k*64 + c]      = Wf[idx];
                ws[k*64 + 32 + c] = Wg[idx];
            }
        } else {
            const float* whp = Wh + (ph-1)*64;
            #pragma unroll
            for (int s = 0; s < 64; s++) {
                int idx = t + 256*s;
                int k = idx >> 6, c = idx & 63;
                ws[k*64 + c] = whp[k*NC + c];
            }
        }
        __syncthreads();

        float acc[4][4];
        #pragma unroll
        for (int a=0;a<4;a++)
            #pragma unroll
            for (int q=0;q<4;q++) acc[a][q]=0.f;

        #pragma unroll 4
        for (int k = 0; k < 256; k++) {
            float4 wv = *(const float4*)&ws[k*64 + c0];
            float xv[4];
            #pragma unroll
            for (int rr=0; rr<4; rr++) xv[rr] = xs[(r0+rr)*257 + k];
            #pragma unroll
            for (int rr=0; rr<4; rr++) {
                acc[rr][0] = fmaf(xv[rr], wv.x, acc[rr][0]);
                acc[rr][1] = fmaf(xv[rr], wv.y, acc[rr][1]);
                acc[rr][2] = fmaf(xv[rr], wv.z, acc[rr][2]);
                acc[rr][3] = fmaf(xv[rr], wv.w, acc[rr][3]);
            }
        }

        if (ph == 0) {
            __syncthreads();   // done reading ws; reuse as staging
            float* sfhi = ws;              // [64][33]
            float* sflo = ws + 64*33;      // [64][33]
            #pragma unroll
            for (int rr = 0; rr < 4; rr++) {
                int lrow = r0 + rr;
                int grow = R0 + lrow;
                #pragma unroll
                for (int q = 0; q < 4; q++) {
                    int c = c0 + q;
                    float val = acc[rr][q] + ((c < 32) ? bf[c] : bg[c-32]);
                    float hi = tf32r(val);
                    float lo = tf32r(val - hi);
                    if (c < 32) {
                        sfhi[lrow*33 + c] = hi;
                        sflo[lrow*33 + c] = lo;
                    } else {
                        d_ghi[grow*ND + (c-32)] = hi;
                        d_glo[grow*ND + (c-32)] = lo;
                    }
                }
            }
            __syncthreads();
            // write f^T [d][key] coalesced
            {
                int dd = t >> 3, part = t & 7;
                size_t dst = ((size_t)bb*ND + dd)*NN + key0 + part*8;
                #pragma unroll
                for (int j = 0; j < 2; j++) {
                    float4 hv, lv;
                    int k0 = part*8 + j*4;
                    hv.x = sfhi[(k0+0)*33 + dd]; hv.y = sfhi[(k0+1)*33 + dd];
                    hv.z = sfhi[(k0+2)*33 + dd]; hv.w = sfhi[(k0+3)*33 + dd];
                    lv.x = sflo[(k0+0)*33 + dd]; lv.y = sflo[(k0+1)*33 + dd];
                    lv.z = sflo[(k0+2)*33 + dd]; lv.w = sflo[(k0+3)*33 + dd];
                    *(float4*)(d_fThi + dst + j*4) = hv;
                    *(float4*)(d_fTlo + dst + j*4) = lv;
                }
            }
        } else {
            #pragma unroll
            for (int rr = 0; rr < 4; rr++) {
                int grow = R0 + r0 + rr;
                #pragma unroll
                for (int q = 0; q < 4; q++) {
                    int c = (ph-1)*64 + c0 + q;
                    d_h[(size_t)grow*NC + c] = tf32r(acc[rr][q] + bh[c]);
                }
            }
        }
    }
}

// ============================================================================
// Flash attention on mma.sync tf32. Grid (NN/64, NB), 256 threads.
// ============================================================================
#define FT_STRIDE 72
#define FT_TILE   (32*FT_STRIDE)          // 2304 floats
#define H_STRIDE  264
#define H_TILE    (64*H_STRIDE)           // 16896 floats
#define P_STRIDE  68
#define OFF_FT    0
#define OFF_H     (OFF_FT + 4*FT_TILE)    // 9216
#define OFF_P     (OFF_H + 2*H_TILE)      // 43008
#define OFF_LSUM  (OFF_P + 64*P_STRIDE)   // 47360
#define ATT_SMEM_BYTES ((OFF_LSUM + 128)*4)

__device__ __forceinline__ void load_tile(uint32_t smb, int bb, int kb, int buf, int t) {
    #pragma unroll
    for (int arr = 0; arr < 2; arr++) {
        const float* src = (arr ? d_fTlo : d_fThi) + (size_t)bb*ND*NN;
        uint32_t dstb = smb + (uint32_t)(OFF_FT + (buf*2+arr)*FT_TILE)*4;
        #pragma unroll
        for (int s = 0; s < 2; s++) {
            int idx = t + 256*s;          // 0..511
            int d = idx >> 4, k4 = idx & 15;
            cpa16(dstb + (uint32_t)(d*FT_STRIDE + k4*4)*4,
                  src + (size_t)d*NN + kb*64 + k4*4);
        }
    }
    const float* hsrc = d_h + ((size_t)(bb*NN + kb*64))*NC;
    uint32_t dsth = smb + (uint32_t)(OFF_H + buf*H_TILE)*4;
    #pragma unroll
    for (int s = 0; s < 16; s++) {
        int idx = t + 256*s;              // 0..4095
        int k = idx >> 6, c4 = idx & 63;
        cpa16(dsth + (uint32_t)(k*H_STRIDE + c4*4)*4, hsrc + k*NC + c4*4);
    }
}

__global__ __launch_bounds__(256, 1) void attn_kernel(
    const float* __restrict__ x, float* __restrict__ out)
{
    extern __shared__ float sm[];
    const uint32_t smb = smem_u32(sm);
    const int t    = threadIdx.x;
    const int w    = t >> 5, lane = t & 31;
    const int g    = lane >> 2, tq = lane & 3;
    const int bb   = blockIdx.y;
    const int q0   = blockIdx.x * BM;

    const int qg = w >> 1, kg = w & 1;    // QK mapping: 4 qgroups x 2 kgroups
    const int mg = w >> 2, ng = w & 3;    // PV mapping: 2 mgroups x 4 ngroups

    float* P  = sm + OFF_P;
    float* LS = sm + OFF_LSUM;
    if (t < 128) LS[t] = 0.f;

    // hoisted QK A fragments (g hi/lo), constant across key tiles
    uint32_t ahi[4][4], alo[4][4];
    {
        const float* gh = d_ghi + ((size_t)(bb*NN + q0 + qg*16))*ND;
        const float* gl = d_glo + ((size_t)(bb*NN + q0 + qg*16))*ND;
        #pragma unroll
        for (int ks = 0; ks < 4; ks++) {
            int c = ks*8 + tq;
            ahi[ks][0] = ldu(gh + g*ND + c);
            ahi[ks][1] = ldu(gh + (g+8)*ND + c);
            ahi[ks][2] = ldu(gh + g*ND + c + 4);
            ahi[ks][3] = ldu(gh + (g+8)*ND + c + 4);
            alo[ks][0] = ldu(gl + g*ND + c);
            alo[ks][1] = ldu(gl + (g+8)*ND + c);
            alo[ks][2] = ldu(gl + g*ND + c + 4);
            alo[ks][3] = ldu(gl + (g+8)*ND + c + 4);
        }
    }

    float oacc[2][8][4];
    #pragma unroll
    for (int a=0;a<2;a++)
        #pragma unroll
        for (int b2=0;b2<8;b2++)
            #pragma unroll
            for (int c=0;c<4;c++) oacc[a][b2][c]=0.f;

    load_tile(smb, bb, 0, 0, t);
    cpa_commit();

    for (int kb = 0; kb < NN/BN; kb++) {
        const int pb = kb & 1;
        if (kb + 1 < NN/BN) load_tile(smb, bb, kb+1, pb^1, t);
        cpa_commit();
        cpa_wait<1>();
        __syncthreads();

        // ---- QK: S(16q x 32k per warp) = compensated tf32 ----
        const float* fthi = sm + OFF_FT + (pb*2+0)*FT_TILE;
        const float* ftlo = sm + OFF_FT + (pb*2+1)*FT_TILE;
        float sacc[4][4];
        #pragma unroll
        for (int nt=0;nt<4;nt++)
            #pragma unroll
            for (int c=0;c<4;c++) sacc[nt][c]=0.f;

        #pragma unroll
        for (int ks = 0; ks < 4; ks++) {
            #pragma unroll
            for (int nt = 0; nt < 4; nt++) {
                int key = kg*32 + nt*8 + g;
                uint32_t bh[2], bl[2];
                bh[0] = ldu(fthi + (ks*8+tq)*FT_STRIDE + key);
                bh[1] = ldu(fthi + (ks*8+tq+4)*FT_STRIDE + key);
                bl[0] = ldu(ftlo + (ks*8+tq)*FT_STRIDE + key);
                bl[1] = ldu(ftlo + (ks*8+tq+4)*FT_STRIDE + key);
                mma8(sacc[nt], ahi[ks], bh);
                mma8(sacc[nt], ahi[ks], bl);
                mma8(sacc[nt], alo[ks], bh);
            }
        }

        // ---- exp, row sums, P store (tf32-rounded) ----
        float rs0 = 0.f, rs1 = 0.f;
        #pragma unroll
        for (int nt = 0; nt < 4; nt++) {
            float p0 = tf32r(__expf(sacc[nt][0]));
            float p1 = tf32r(__expf(sacc[nt][1]));
            float p2 = tf32r(__expf(sacc[nt][2]));
            float p3 = tf32r(__expf(sacc[nt][3]));
            rs0 += p0 + p1;
            rs1 += p2 + p3;
            int col = kg*32 + nt*8 + 2*tq;
            *(float2*)&P[(qg*16+g  )*P_STRIDE + col] = make_float2(p0, p1);
            *(float2*)&P[(qg*16+g+8)*P_STRIDE + col] = make_float2(p2, p3);
        }
        rs0 += __shfl_xor_sync(0xffffffffu, rs0, 1);
        rs0 += __shfl_xor_sync(0xffffffffu, rs0, 2);
        rs1 += __shfl_xor_sync(0xffffffffu, rs1, 1);
        rs1 += __shfl_xor_sync(0xffffffffu, rs1, 2);
        if (tq == 0) {
            LS[kg*64 + qg*16 + g    ] += rs0;
            LS[kg*64 + qg*16 + g + 8] += rs1;
        }
        __syncthreads();

        // ---- PV: O(32q x 64c per warp) += P * H ----
        const float* hb = sm + OFF_H + pb*H_TILE;
        #pragma unroll
        for (int ks = 0; ks < 8; ks++) {
            uint32_t pa[2][4];
            #pragma unroll
            for (int mt = 0; mt < 2; mt++) {
                const float* Pr = P + (mg*32 + mt*16)*P_STRIDE + ks*8;
                pa[mt][0] = ldu(Pr + g*P_STRIDE + tq);
                pa[mt][1] = ldu(Pr + (g+8)*P_STRIDE + tq);
                pa[mt][2] = ldu(Pr + g*P_STRIDE + tq + 4);
                pa[mt][3] = ldu(Pr + (g+8)*P_STRIDE + tq + 4);
            }
            #pragma unroll
            for (int nt = 0; nt < 8; nt++) {
                int col = ng*64 + nt*8 + g;
                uint32_t hbf[2];
                hbf[0] = ldu(hb + (ks*8+tq)*H_STRIDE + col);
                hbf[1] = ldu(hb + (ks*8+tq+4)*H_STRIDE + col);
                mma8(oacc[0][nt], pa[0], hbf);
                mma8(oacc[1][nt], pa[1], hbf);
            }
        }
        __syncthreads();
    }

    // ---- epilogue: out = x + O / l ----
    #pragma unroll
    for (int mt = 0; mt < 2; mt++) {
        int r0 = mg*32 + mt*16 + g;
        float inv0 = 1.0f / (LS[r0    ] + LS[64 + r0    ]);
        float inv1 = 1.0f / (LS[r0 + 8] + LS[64 + r0 + 8]);
        #pragma unroll
        for (int nt = 0; nt < 8; nt++) {
            int col = ng*64 + nt*8 + 2*tq;
            size_t base0 = ((size_t)(bb*NN + q0 + r0))*NC + col;
            size_t base1 = base0 + (size_t)8*NC;
            float2 xv0 = *(const float2*)(x + base0);
            float2 xv1 = *(const float2*)(x + base1);
            float2 o0, o1;
            o0.x = xv0.x + oacc[mt][nt][0]*inv0;
            o0.y = xv0.y + oacc[mt][nt][1]*inv0;
            o1.x = xv1.x + oacc[mt][nt][2]*inv1;
            o1.y = xv1.y + oacc[mt][nt][3]*inv1;
            *(float2*)(out + base0) = o0;
            *(float2*)(out + base1) = o1;
        }
    }
}

extern "C" void kernel_launch(void* const* d_in, const int* in_sizes, int n_in,
                              void* d_out, int out_size) {
    (void)in_sizes; (void)n_in; (void)out_size;
    const float* x  = (const float*)d_in[0];
    const float* Wf = (const float*)d_in[1];
    const float* bf = (const float*)d_in[2];
    const float* Wg = (const float*)d_in[3];
    const float* bg = (const float*)d_in[4];
    const float* Wh = (const float*)d_in[5];
    const float* bh = (const float*)d_in[6];
    float* out = (float*)d_out;

    cudaFuncSetAttribute(proj_kernel, cudaFuncAttributeMaxDynamicSharedMemorySize,
                         PROJ_SMEM_BYTES);
    cudaFuncSetAttribute(attn_kernel, cudaFuncAttributeMaxDynamicSharedMemorySize,
                         ATT_SMEM_BYTES);

    proj_kernel<<<(NB*NN)/64, 256, PROJ_SMEM_BYTES>>>(x, Wf, bf, Wg, bg, Wh, bh);

    dim3 grid(NN/BM, NB);
    attn_kernel<<<grid, 256, ATT_SMEM_BYTES>>>(x, out);
}

// round 4
// speedup vs baseline: 3.3920x; 1.1342x over previous
#include <cuda_runtime.h>
#include <cstdint>

#define NB 4
#define NN 4096
#define ND 32
#define NC 256
#define BM 128
#define BN 64
#define NT (NN/BN)

// ---------------- scratch (device globals; allocation-free rule) -----------
__device__ float  d_ghi[NB*NN*ND];        // g rounded rna-tf32
__device__ float  d_glo[NB*NN*ND];        // rna(g - g_hi)
__device__ float2 d_fp_hi[NB*16*NN];      // f^T pair rows: [b][dp][key] = (fT[d1][k], fT[d1+4][k])
__device__ float2 d_fp_lo[NB*16*NN];
__device__ float2 d_hp[NB*(NN/2)*NC];     // h pair rows: [b][kp][c] = (h[k1][c], h[k1+4][c])

// ---------------- helpers ---------------------------------------------------
__device__ __forceinline__ uint32_t smem_u32(const void* p) {
    return (uint32_t)__cvta_generic_to_shared(p);
}
__device__ __forceinline__ void cpa16(uint32_t dst, const void* src) {
    asm volatile("cp.async.cg.shared.global [%0], [%1], 16;" :: "r"(dst), "l"(src));
}
__device__ __forceinline__ void cpa_commit() {
    asm volatile("cp.async.commit_group;" ::: "memory");
}
template<int N> __device__ __forceinline__ void cpa_wait() {
    asm volatile("cp.async.wait_group %0;" :: "n"(N) : "memory");
}
__device__ __forceinline__ float tf32r(float v) {
    uint32_t r;
    asm("cvt.rna.tf32.f32 %0, %1;" : "=r"(r) : "f"(v));
    return __uint_as_float(r);
}
__device__ __forceinline__ void mma8(float* c, const uint32_t* a, uint32_t b0, uint32_t b1) {
    asm volatile("mma.sync.aligned.m16n8k8.row.col.f32.tf32.tf32.f32 "
        "{%0,%1,%2,%3}, {%4,%5,%6,%7}, {%8,%9}, {%0,%1,%2,%3};"
        : "+f"(c[0]), "+f"(c[1]), "+f"(c[2]), "+f"(c[3])
        : "r"(a[0]), "r"(a[1]), "r"(a[2]), "r"(a[3]), "r"(b0), "r"(b1));
}
__device__ __forceinline__ void mma8f2(float* c, const uint32_t* a, float2 b) {
    mma8(c, a, __float_as_uint(b.x), __float_as_uint(b.y));
}
__device__ __forceinline__ uint32_t ldu(const float* p) {
    return __float_as_uint(*p);
}
// packed f32x2
__device__ __forceinline__ unsigned long long pk2(float a, float b) {
    unsigned long long r;
    asm("mov.b64 %0, {%1, %2};" : "=l"(r) : "f"(a), "f"(b));
    return r;
}
__device__ __forceinline__ void fma2(unsigned long long& d, unsigned long long a, unsigned long long b) {
    asm("fma.rn.f32x2 %0, %1, %2, %0;" : "+l"(d) : "l"(a), "l"(b));
}
__device__ __forceinline__ void unpk2(unsigned long long v, float& a, float& b) {
    asm("mov.b64 {%0, %1}, %2;" : "=f"(a), "=f"(b) : "l"(v));
}

// ============================================================================
// Projection kernel: 256 CTAs x 256 threads, 64 rows each. f32x2 FMA.
// Outputs: g hi/lo (row-major), f^T pairs (hi/lo), h pairs.
// ============================================================================
#define PROJ_SMEM_BYTES ((64*257 + 256*64)*4)

__global__ __launch_bounds__(256) void proj_kernel(
    const float* __restrict__ x,
    const float* __restrict__ Wf, const float* __restrict__ bf,
    const float* __restrict__ Wg, const float* __restrict__ bg,
    const float* __restrict__ Wh, const float* __restrict__ bh)
{
    extern __shared__ float sm[];
    float* xs = sm;               // [64][257]
    float* ws = sm + 64*257;      // [256][64]; reused for staging
    const int t    = threadIdx.x;
    const int R0   = blockIdx.x * 64;
    const int bb   = R0 >> 12;
    const int key0 = R0 & (NN-1);

    {
        const float4* xg = (const float4*)(x + (size_t)R0*NC);
        #pragma unroll
        for (int s = 0; s < 16; s++) {
            int idx = t + 256*s;
            int row = idx >> 6, k4 = idx & 63;
            float4 v = xg[idx];
            float* dst = &xs[row*257 + k4*4];
            dst[0]=v.x; dst[1]=v.y; dst[2]=v.z; dst[3]=v.w;
        }
    }

    const int c0 = (t & 15) * 4;
    const int r0 = (t >> 4) * 4;

    for (int ph = 0; ph < 5; ph++) {
        __syncthreads();
        if (ph == 0) {
            #pragma unroll
            for (int s = 0; s < 32; s++) {
                int idx = t + 256*s;
                int k = idx >> 5, c = idx & 31;
                ws[k*64 + c]      = Wf[idx];
                ws[k*64 + 32 + c] = Wg[idx];
            }
        } else {
            const float* whp = Wh + (ph-1)*64;
            #pragma unroll
            for (int s = 0; s < 64; s++) {
                int idx = t + 256*s;
                int k = idx >> 6, c = idx & 63;
                ws[k*64 + c] = whp[k*NC + c];
            }
        }
        __syncthreads();

        unsigned long long accA[4], accB[4];
        #pragma unroll
        for (int a = 0; a < 4; a++) { accA[a] = 0ull; accB[a] = 0ull; }

        #pragma unroll 4
        for (int k = 0; k < 256; k++) {
            float4 wv = *(const float4*)&ws[k*64 + c0];
            unsigned long long wA = pk2(wv.x, wv.y);
            unsigned long long wB = pk2(wv.z, wv.w);
            #pragma unroll
            for (int rr = 0; rr < 4; rr++) {
                float xv = xs[(r0+rr)*257 + k];
                unsigned long long xb = pk2(xv, xv);
                fma2(accA[rr], xb, wA);
                fma2(accB[rr], xb, wB);
            }
        }

        if (ph == 0) {
            __syncthreads();          // done reading ws; reuse as staging
            float* sfhi = ws;                 // [64 keys][33]
            float* sflo = ws + 64*33;         // [64 keys][33]
            #pragma unroll
            for (int rr = 0; rr < 4; rr++) {
                int lrow = r0 + rr;
                int grow = R0 + lrow;
                float v[4];
                unpk2(accA[rr], v[0], v[1]);
                unpk2(accB[rr], v[2], v[3]);
                #pragma unroll
                for (int q = 0; q < 4; q++) {
                    int c = c0 + q;
                    float val = v[q] + ((c < 32) ? bf[c] : bg[c-32]);
                    float hi = tf32r(val);
                    float lo = tf32r(val - hi);
                    if (c < 32) {
                        sfhi[lrow*33 + c] = hi;
                        sflo[lrow*33 + c] = lo;
                    } else {
                        d_ghi[grow*ND + (c-32)] = hi;
                        d_glo[grow*ND + (c-32)] = lo;
                    }
                }
            }
            __syncthreads();
            // paired write of f^T: dp = ks*4+tq <-> rows (d1, d1+4)
            #pragma unroll
            for (int j = 0; j < 4; j++) {
                int idx = t + 256*j;          // 0..1023
                int dp = idx >> 6, key_loc = idx & 63;
                int d1 = ((dp >> 2) << 3) + (dp & 3);
                size_t dst = ((size_t)(bb*16 + dp))*NN + key0 + key_loc;
                d_fp_hi[dst] = make_float2(sfhi[key_loc*33 + d1], sfhi[key_loc*33 + d1 + 4]);
                d_fp_lo[dst] = make_float2(sflo[key_loc*33 + d1], sflo[key_loc*33 + d1 + 4]);
            }
        } else {
            __syncthreads();          // done reading ws; reuse as h staging
            float* sh = ws;                   // [64 keys][65]
            #pragma unroll
            for (int rr = 0; rr < 4; rr++) {
                int lrow = r0 + rr;
                float v[4];
                unpk2(accA[rr], v[0], v[1]);
                unpk2(accB[rr], v[2], v[3]);
                #pragma unroll
                for (int q = 0; q < 4; q++) {
                    int c = c0 + q;
                    sh[lrow*65 + c] = tf32r(v[q] + bh[(ph-1)*64 + c]);
                }
            }
            __syncthreads();
            // paired write of h: kp = (k>>3)*4 + (k&3) <-> keys (k1, k1+4)
            #pragma unroll
            for (int j = 0; j < 8; j++) {
                int idx = t + 256*j;          // 0..2047
                int kp = idx >> 6, c_loc = idx & 63;
                int k1 = ((kp >> 2) << 3) + (kp & 3);
                size_t dst = ((size_t)(bb*(NN/2)) + (key0 >> 1) + kp)*NC + (ph-1)*64 + c_loc;
                d_hp[dst] = make_float2(sh[k1*65 + c_loc], sh[(k1+4)*65 + c_loc]);
            }
        }
    }
}

// ============================================================================
// Flash attention, mma.sync tf32. Grid (NN/128, NB) = (32,4) = 128 CTAs,
// 512 threads (16 warps). BM=128 queries, BN=64 keys per tile.
// QK: warp = 16q x 32k (qg = w>>1, kg = w&1), 3-term compensated tf32.
// PV: warp = 32q x 64c (mg = w>>2, ng = w&3).
// ============================================================================
#define FP_TILE   2176                        // 16 rows x 136 floats
#define FP_OFF(buf, arr) (((buf)*2 + (arr))*FP_TILE)
#define HP_STRIDE 520
#define HP_TILE   (32*HP_STRIDE)              // 16640 floats
#define OFF_HP    (4*FP_TILE)                 // 8704
#define P_STRIDE  68
#define OFF_P     (OFF_HP + 2*HP_TILE)        // 41984
#define OFF_LS    (OFF_P + 128*P_STRIDE)      // 50688
#define ATT_SMEM_FLOATS (OFF_LS + 256)
#define ATT_SMEM_BYTES  (ATT_SMEM_FLOATS*4)

__device__ __forceinline__ void attn_load_tile(uint32_t smb, int bb, int kb, int buf, int t) {
    // f^T pairs hi/lo: 1024 cpa16
    #pragma unroll
    for (int s = 0; s < 2; s++) {
        int idx = t + 512*s;
        int arr = idx >> 9, rem = idx & 511;
        int row = rem >> 5, q4 = rem & 31;
        const float2* src = (arr ? d_fp_lo : d_fp_hi)
                          + ((size_t)(bb*16 + row))*NN + kb*64 + q4*2;
        cpa16(smb + 4u*(uint32_t)(FP_OFF(buf,arr) + row*136 + q4*4), src);
    }
    // h pairs: 4096 cpa16
    #pragma unroll
    for (int s = 0; s < 8; s++) {
        int idx = t + 512*s;
        int row = idx >> 7, c4 = idx & 127;
        const float2* src = d_hp + ((size_t)(bb*(NN/2) + kb*32 + row))*NC + c4*2;
        cpa16(smb + 4u*(uint32_t)(OFF_HP + buf*HP_TILE + row*HP_STRIDE + c4*4), src);
    }
}

__global__ __launch_bounds__(512, 1) void attn_kernel(
    const float* __restrict__ x, float* __restrict__ out)
{
    extern __shared__ float sm[];
    const uint32_t smb = smem_u32(sm);
    const int t    = threadIdx.x;
    const int w    = t >> 5, lane = t & 31;
    const int g    = lane >> 2, tq = lane & 3;
    const int bb   = blockIdx.y;
    const int q0   = blockIdx.x * BM;

    const int qg = w >> 1, kg = w & 1;    // QK: 8 qgroups x 2 kgroups
    const int mg = w >> 2, ng = w & 3;    // PV: 4 mgroups x 4 ngroups

    float* P  = sm + OFF_P;
    float* LS = sm + OFF_LS;
    if (t < 256) LS[t] = 0.f;

    // hoisted QK A fragments (g hi/lo)
    uint32_t ahi[4][4], alo[4][4];
    {
        const float* gh = d_ghi + ((size_t)(bb*NN + q0 + qg*16))*ND;
        const float* gl = d_glo + ((size_t)(bb*NN + q0 + qg*16))*ND;
        #pragma unroll
        for (int ks = 0; ks < 4; ks++) {
            int c = ks*8 + tq;
            ahi[ks][0] = ldu(gh + g*ND + c);
            ahi[ks][1] = ldu(gh + (g+8)*ND + c);
            ahi[ks][2] = ldu(gh + g*ND + c + 4);
            ahi[ks][3] = ldu(gh + (g+8)*ND + c + 4);
            alo[ks][0] = ldu(gl + g*ND + c);
            alo[ks][1] = ldu(gl + (g+8)*ND + c);
            alo[ks][2] = ldu(gl + g*ND + c + 4);
            alo[ks][3] = ldu(gl + (g+8)*ND + c + 4);
        }
    }

    float oacc[2][8][4];
    #pragma unroll
    for (int a=0;a<2;a++)
        #pragma unroll
        for (int b2=0;b2<8;b2++)
            #pragma unroll
            for (int c=0;c<4;c++) oacc[a][b2][c]=0.f;

    attn_load_tile(smb, bb, 0, 0, t);
    cpa_commit();

    #pragma unroll 1
    for (int kb = 0; kb < NT; kb++) {
        const int pb = kb & 1;
        if (kb + 1 < NT) attn_load_tile(smb, bb, kb+1, pb^1, t);
        cpa_commit();                 // (empty group on last iter keeps wait<1> correct)
        cpa_wait<1>();
        __syncthreads();

        // ---- QK: S(16q x 32k per warp), compensated tf32 ----
        const float* fph = sm + FP_OFF(pb, 0);
        const float* fpl = sm + FP_OFF(pb, 1);
        float sacc[4][4];
        #pragma unroll
        for (int nt=0;nt<4;nt++)
            #pragma unroll
            for (int c=0;c<4;c++) sacc[nt][c]=0.f;

        #pragma unroll
        for (int ks = 0; ks < 4; ks++) {
            const float* fh = fph + (ks*4+tq)*136;
            const float* fl = fpl + (ks*4+tq)*136;
            #pragma unroll
            for (int nt = 0; nt < 4; nt++) {
                int key = kg*32 + nt*8 + g;
                float2 bh2 = *(const float2*)(fh + key*2);
                float2 bl2 = *(const float2*)(fl + key*2);
                mma8f2(sacc[nt], ahi[ks], bh2);
                mma8f2(sacc[nt], ahi[ks], bl2);
                mma8f2(sacc[nt], alo[ks], bh2);
            }
        }

        // ---- exp, row sums, P store (tf32-rounded) ----
        float rs0 = 0.f, rs1 = 0.f;
        #pragma unroll
        for (int nt = 0; nt < 4; nt++) {
            float p0 = tf32r(__expf(sacc[nt][0]));
            float p1 = tf32r(__expf(sacc[nt][1]));
            float p2 = tf32r(__expf(sacc[nt][2]));
            float p3 = tf32r(__expf(sacc[nt][3]));
            rs0 += p0 + p1;
            rs1 += p2 + p3;
            int colb = kg*32 + nt*8 + 2*tq;
            *(float2*)&P[(qg*16+g  )*P_STRIDE + colb] = make_float2(p0, p1);
            *(float2*)&P[(qg*16+g+8)*P_STRIDE + colb] = make_float2(p2, p3);
        }
        rs0 += __shfl_xor_sync(0xffffffffu, rs0, 1);
        rs0 += __shfl_xor_sync(0xffffffffu, rs0, 2);
        rs1 += __shfl_xor_sync(0xffffffffu, rs1, 1);
        rs1 += __shfl_xor_sync(0xffffffffu, rs1, 2);
        if (tq == 0) {
            LS[kg*128 + qg*16 + g    ] += rs0;
            LS[kg*128 + qg*16 + g + 8] += rs1;
        }
        __syncthreads();

        // ---- PV: O(32q x 64c per warp) += P * H ----
        const float* hpb = sm + OFF_HP + pb*HP_TILE;
        #pragma unroll
        for (int ks = 0; ks < 8; ks++) {
            uint32_t pa[2][4];
            #pragma unroll
            for (int mt = 0; mt < 2; mt++) {
                const float* Pr = P + (mg*32 + mt*16)*P_STRIDE + ks*8;
                pa[mt][0] = ldu(Pr + g*P_STRIDE + tq);
                pa[mt][1] = ldu(Pr + (g+8)*P_STRIDE + tq);
                pa[mt][2] = ldu(Pr + g*P_STRIDE + tq + 4);
                pa[mt][3] = ldu(Pr + (g+8)*P_STRIDE + tq + 4);
            }
            const float* hr = hpb + (ks*4+tq)*HP_STRIDE;
            #pragma unroll
            for (int nt = 0; nt < 8; nt++) {
                int col = ng*64 + nt*8 + g;
                float2 h2 = *(const float2*)(hr + col*2);
                uint32_t b0 = __float_as_uint(h2.x), b1 = __float_as_uint(h2.y);
                mma8(oacc[0][nt], pa[0], b0, b1);
                mma8(oacc[1][nt], pa[1], b0, b1);
            }
        }
        __syncthreads();
    }

    // ---- epilogue: out = x + O / l ----
    #pragma unroll
    for (int mt = 0; mt < 2; mt++) {
        int r0 = mg*32 + mt*16 + g;
        float inv0 = 1.0f / (LS[r0    ] + LS[128 + r0    ]);
        float inv1 = 1.0f / (LS[r0 + 8] + LS[128 + r0 + 8]);
        #pragma unroll
        for (int nt = 0; nt < 8; nt++) {
            int col = ng*64 + nt*8 + 2*tq;
            size_t base0 = ((size_t)(bb*NN + q0 + r0))*NC + col;
            size_t base1 = base0 + (size_t)8*NC;
            float2 xv0 = *(const float2*)(x + base0);
            float2 xv1 = *(const float2*)(x + base1);
            float2 o0, o1;
            o0.x = xv0.x + oacc[mt][nt][0]*inv0;
            o0.y = xv0.y + oacc[mt][nt][1]*inv0;
            o1.x = xv1.x + oacc[mt][nt][2]*inv1;
            o1.y = xv1.y + oacc[mt][nt][3]*inv1;
            *(float2*)(out + base0) = o0;
            *(float2*)(out + base1) = o1;
        }
    }
}

extern "C" void kernel_launch(void* const* d_in, const int* in_sizes, int n_in,
                              void* d_out, int out_size) {
    (void)in_sizes; (void)n_in; (void)out_size;
    const float* x  = (const float*)d_in[0];
    const float* Wf = (const float*)d_in[1];
    const float* bf = (const float*)d_in[2];
    const float* Wg = (const float*)d_in[3];
    const float* bg = (const float*)d_in[4];
    const float* Wh = (const float*)d_in[5];
    const float* bh = (const float*)d_in[6];
    float* out = (float*)d_out;

    cudaFuncSetAttribute(proj_kernel, cudaFuncAttributeMaxDynamicSharedMemorySize,
                         PROJ_SMEM_BYTES);
    cudaFuncSetAttribute(attn_kernel, cudaFuncAttributeMaxDynamicSharedMemorySize,
                         ATT_SMEM_BYTES);

    proj_kernel<<<(NB*NN)/64, 256, PROJ_SMEM_BYTES>>>(x, Wf, bf, Wg, bg, Wh, bh);

    dim3 grid(NN/BM, NB);
    attn_kernel<<<grid, 512, ATT_SMEM_BYTES>>>(x, out);
}